// round 1
// baseline (speedup 1.0000x reference)
#include <cuda_runtime.h>
#include <math.h>

// Problem constants
#define B_   64
#define S_   512
#define D_   1024
#define H_   1024
#define G4   (4 * H_)        // 4096
#define M_TOT (B_ * S_)      // 32768

// Scratch (allocation-free rule: __device__ globals)
__device__ float g_xg[(size_t)S_ * B_ * G4];   // [S][B][4H]  = 512 MB
__device__ float g_c[B_ * H_];                 // cell state  [B][H]

// ---------------------------------------------------------------------------
// Kernel A: input projection  xg[s][b][n] = sum_k x[m][k]*Wi[n][k] + bi[n]
//           where m = b*S + s  (x is [B,S,D] row-major => flat [M][K])
// Tile: 128(M) x 64(N), TK=16, 256 threads, 8x4 per-thread register tile.
// ---------------------------------------------------------------------------
#define IT_M 128
#define IT_N 64
#define IT_K 16

__global__ __launch_bounds__(256)
void input_gemm(const float* __restrict__ x,
                const float* __restrict__ Wi,
                const float* __restrict__ bi)
{
    __shared__ float As[IT_K][IT_M + 4];  // row len 132 floats (16B-aligned rows)
    __shared__ float Bs[IT_K][IT_N + 4];  // row len 68 floats

    const int m0 = blockIdx.y * IT_M;
    const int n0 = blockIdx.x * IT_N;
    const int tx = threadIdx.x;
    const int tn = tx & 15;   // 16 cols * 4  = 64
    const int tm = tx >> 4;   // 16 rows * 8  = 128

    float acc[8][4];
#pragma unroll
    for (int i = 0; i < 8; ++i)
#pragma unroll
        for (int j = 0; j < 4; ++j) acc[i][j] = 0.0f;

    for (int k0 = 0; k0 < D_; k0 += IT_K) {
        // Load A tile: 128 rows x 16 k = 512 float4, 2 per thread (transposed store)
#pragma unroll
        for (int l = 0; l < 2; ++l) {
            int q   = tx * 2 + l;           // 0..511
            int row = q >> 2;               // 4 float4 per row
            int c4  = (q & 3) * 4;
            float4 v = *(const float4*)(x + (size_t)(m0 + row) * D_ + k0 + c4);
            As[c4 + 0][row] = v.x;
            As[c4 + 1][row] = v.y;
            As[c4 + 2][row] = v.z;
            As[c4 + 3][row] = v.w;
        }
        // Load B tile: 64 rows x 16 k = 256 float4, 1 per thread
        {
            int q   = tx;
            int row = q >> 2;
            int c4  = (q & 3) * 4;
            float4 v = *(const float4*)(Wi + (size_t)(n0 + row) * D_ + k0 + c4);
            Bs[c4 + 0][row] = v.x;
            Bs[c4 + 1][row] = v.y;
            Bs[c4 + 2][row] = v.z;
            Bs[c4 + 3][row] = v.w;
        }
        __syncthreads();

#pragma unroll
        for (int k = 0; k < IT_K; ++k) {
            float a[8], b[4];
            *(float4*)&a[0] = *(const float4*)&As[k][tm * 8];
            *(float4*)&a[4] = *(const float4*)&As[k][tm * 8 + 4];
            *(float4*)&b[0] = *(const float4*)&Bs[k][tn * 4];
#pragma unroll
            for (int i = 0; i < 8; ++i)
#pragma unroll
                for (int j = 0; j < 4; ++j)
                    acc[i][j] += a[i] * b[j];
        }
        __syncthreads();
    }

    // Epilogue: add bias, scatter to g_xg[s][b][n]
    float4 biv = *(const float4*)(bi + n0 + tn * 4);
#pragma unroll
    for (int i = 0; i < 8; ++i) {
        int m  = m0 + tm * 8 + i;
        int s  = m & (S_ - 1);      // m % 512
        int bb = m >> 9;            // m / 512
        float4 o;
        o.x = acc[i][0] + biv.x;
        o.y = acc[i][1] + biv.y;
        o.z = acc[i][2] + biv.z;
        o.w = acc[i][3] + biv.w;
        *(float4*)(g_xg + ((size_t)s * B_ + bb) * G4 + n0 + tn * 4) = o;
    }
}

// ---------------------------------------------------------------------------
// Kernel B: one LSTM timestep.
// Each CTA owns 8 hidden units => 32 gate columns (i,f,g,o x 8).
// GEMM tile: M=64(batch) x N=32, K=H_=1024 (TK=32), 128 threads, 4x4 reg tile.
// Then CTA-local cell update; h written into hidden_seq (d_out), c into g_c.
// ---------------------------------------------------------------------------
#define RT_K 32

__global__ __launch_bounds__(128)
void lstm_step(const float* __restrict__ hp, size_t hstride,   // h_{t-1}: hp + b*hstride + k   (hstride=0 => broadcast h0)
               const float* __restrict__ Wh,
               const float* __restrict__ bh,
               const float* __restrict__ c0, int c_bcast,      // t==0: read c0[j] broadcast
               float* __restrict__ hidden,                     // d_out hidden_seq base [B][S][H]
               int t)
{
    __shared__ float Hs[RT_K][64 + 4];   // [k][b]
    __shared__ float Ws[RT_K][32 + 4];   // [k][n_local]
    __shared__ float Gs[64][36];         // gates [b][n_local], row = 144B (16B-aligned)

    const int j0 = blockIdx.x * 8;       // 128 CTAs x 8 hidden units
    const int tx = threadIdx.x;
    const int tn = tx & 7;               // 8 * 4  = 32
    const int tm = tx >> 3;              // 16 * 4 = 64

    float acc[4][4];
#pragma unroll
    for (int i = 0; i < 4; ++i)
#pragma unroll
        for (int j = 0; j < 4; ++j) acc[i][j] = 0.0f;

    for (int k0 = 0; k0 < H_; k0 += RT_K) {
        // Hs: 64 rows(b) x 32 k = 512 float4, 4 per thread
#pragma unroll
        for (int l = 0; l < 4; ++l) {
            int q   = tx + l * 128;      // 0..511
            int row = q >> 3;            // 8 float4 per row
            int c4  = (q & 7) * 4;
            float4 v = *(const float4*)(hp + (size_t)row * hstride + k0 + c4);
            Hs[c4 + 0][row] = v.x;
            Hs[c4 + 1][row] = v.y;
            Hs[c4 + 2][row] = v.z;
            Hs[c4 + 3][row] = v.w;
        }
        // Ws: 32 rows(n_local) x 32 k = 256 float4, 2 per thread
#pragma unroll
        for (int l = 0; l < 2; ++l) {
            int q    = tx + l * 128;     // 0..255
            int row  = q >> 3;           // n_local 0..31
            int c4   = (q & 7) * 4;
            int gate = row >> 3;
            int j    = j0 + (row & 7);
            float4 v = *(const float4*)(Wh + (size_t)(gate * H_ + j) * H_ + k0 + c4);
            Ws[c4 + 0][row] = v.x;
            Ws[c4 + 1][row] = v.y;
            Ws[c4 + 2][row] = v.z;
            Ws[c4 + 3][row] = v.w;
        }
        __syncthreads();

#pragma unroll
        for (int k = 0; k < RT_K; ++k) {
            float a[4], b[4];
            *(float4*)&a[0] = *(const float4*)&Hs[k][tm * 4];
            *(float4*)&b[0] = *(const float4*)&Ws[k][tn * 4];
#pragma unroll
            for (int i = 0; i < 4; ++i)
#pragma unroll
                for (int j = 0; j < 4; ++j)
                    acc[i][j] += a[i] * b[j];
        }
        __syncthreads();
    }

    // Stash gates to SMEM for the cross-thread cell update
#pragma unroll
    for (int i = 0; i < 4; ++i) {
        float4 o;
        o.x = acc[i][0]; o.y = acc[i][1]; o.z = acc[i][2]; o.w = acc[i][3];
        *(float4*)&Gs[tm * 4 + i][tn * 4] = o;
    }
    __syncthreads();

    // Cell update: 64 b x 8 j = 512 items, 4 per thread
#pragma unroll
    for (int l = 0; l < 4; ++l) {
        int idx = tx + l * 128;
        int bb  = idx >> 3;
        int jj  = idx & 7;
        int j   = j0 + jj;
        size_t xgb = ((size_t)t * B_ + bb) * G4;

        float iv = Gs[bb][ 0 + jj] + g_xg[xgb +          j] + bh[         j];
        float fv = Gs[bb][ 8 + jj] + g_xg[xgb +   H_ +   j] + bh[  H_ +   j];
        float gv = Gs[bb][16 + jj] + g_xg[xgb + 2*H_ +   j] + bh[2*H_ +   j];
        float ov = Gs[bb][24 + jj] + g_xg[xgb + 3*H_ +   j] + bh[3*H_ +   j];

        float is = 1.0f / (1.0f + expf(-iv));
        float fs = 1.0f / (1.0f + expf(-fv));
        float gt = tanhf(gv);
        float os = 1.0f / (1.0f + expf(-ov));

        float cp = c_bcast ? c0[j] : g_c[bb * H_ + j];
        float c  = fs * cp + is * gt;
        g_c[bb * H_ + j] = c;
        hidden[((size_t)bb * S_ + t) * H_ + j] = os * tanhf(c);
    }
}

// ---------------------------------------------------------------------------
// Finalize: copy h_final (= hidden_seq[:,S-1,:]) and c_final into d_out tail.
// ---------------------------------------------------------------------------
__global__ void finalize(const float* __restrict__ hidden, float* __restrict__ out_hc)
{
    int i = blockIdx.x * blockDim.x + threadIdx.x;
    int n = B_ * H_;
    if (i < n) {
        int bb = i / H_, j = i % H_;
        out_hc[i] = hidden[((size_t)bb * S_ + (S_ - 1)) * H_ + j];
    } else if (i < 2 * n) {
        out_hc[i] = g_c[i - n];
    }
}

// ---------------------------------------------------------------------------
extern "C" void kernel_launch(void* const* d_in, const int* in_sizes, int n_in,
                              void* d_out, int out_size)
{
    const float* x  = (const float*)d_in[0];
    const float* h0 = (const float*)d_in[1];
    const float* c0 = (const float*)d_in[2];
    const float* Wi = (const float*)d_in[3];
    const float* bi = (const float*)d_in[4];
    const float* Wh = (const float*)d_in[5];
    const float* bh = (const float*)d_in[6];
    float* out = (float*)d_out;

    // Phase 1: input projection into g_xg
    dim3 g1(G4 / IT_N, M_TOT / IT_M);   // (64, 256)
    input_gemm<<<g1, 256>>>(x, Wi, bi);

    // Phase 2: 512 sequential timesteps (each a graph node)
    for (int t = 0; t < S_; ++t) {
        const float* hp = (t == 0) ? h0 : (out + (size_t)(t - 1) * H_);
        size_t hstride  = (t == 0) ? 0 : (size_t)S_ * H_;
        lstm_step<<<H_ / 8, 128>>>(hp, hstride, Wh, bh, c0, (t == 0) ? 1 : 0, out, t);
    }

    // Phase 3: final (h, c)
    finalize<<<(2 * B_ * H_ + 255) / 256, 256>>>(out, out + (size_t)B_ * S_ * H_);
}

// round 2
// speedup vs baseline: 1.3545x; 1.3545x over previous
#include <cuda_runtime.h>
#include <math.h>

typedef unsigned long long ull;

// Problem constants
#define B_   64
#define S_   512
#define D_   1024
#define H_   1024
#define G4   (4 * H_)        // 4096
#define M_TOT (B_ * S_)      // 32768
#define NCTA 128

// Scratch (allocation-free rule: __device__ globals)
__device__ float g_xg[(size_t)S_ * B_ * G4];   // [S][B][4H]  = 512 MB
__device__ float g_c[B_ * H_];                 // final cell state [B][H]
__device__ float g_hT[2][H_][B_];              // ping-pong h, transposed [j][b]
__device__ unsigned g_bar_sense;               // grid barrier generation
__device__ unsigned g_bar_count;               // grid barrier arrivals

// ---------------------------------------------------------------------------
// Packed fp32x2 helpers (Blackwell FFMA2 — only reachable via PTX)
// ---------------------------------------------------------------------------
__device__ __forceinline__ ull pk2(float lo, float hi) {
    ull r; asm("mov.b64 %0, {%1, %2};" : "=l"(r) : "f"(lo), "f"(hi)); return r;
}
__device__ __forceinline__ ull fma2(ull a, ull b, ull c) {
    ull d; asm("fma.rn.f32x2 %0, %1, %2, %3;" : "=l"(d) : "l"(a), "l"(b), "l"(c)); return d;
}
__device__ __forceinline__ void upk2(ull v, float& lo, float& hi) {
    asm("mov.b64 {%0, %1}, %2;" : "=f"(lo), "=f"(hi) : "l"(v));
}

// ---------------------------------------------------------------------------
// Kernel A: input projection  xg[s][b][n] = sum_k x[m][k]*Wi[n][k] + bi[n]
// Tile 128(M) x 64(N), TK=16, 256 threads, 8x4 per-thread via 4x(Mpair)x4 FFMA2
// ---------------------------------------------------------------------------
#define IT_M 128
#define IT_N 64
#define IT_K 16

__global__ __launch_bounds__(256)
void input_gemm(const float* __restrict__ x,
                const float* __restrict__ Wi,
                const float* __restrict__ bi)
{
    __shared__ float As[IT_K][IT_M + 4];
    __shared__ float Bs[IT_K][IT_N + 4];

    const int m0 = blockIdx.y * IT_M;
    const int n0 = blockIdx.x * IT_N;
    const int tx = threadIdx.x;
    const int tn = tx & 15;
    const int tm = tx >> 4;

    ull acc[4][4];
#pragma unroll
    for (int i = 0; i < 4; ++i)
#pragma unroll
        for (int j = 0; j < 4; ++j) acc[i][j] = 0ULL;

    for (int k0 = 0; k0 < D_; k0 += IT_K) {
#pragma unroll
        for (int l = 0; l < 2; ++l) {
            int q   = tx * 2 + l;
            int row = q >> 2;
            int c4  = (q & 3) * 4;
            float4 v = *(const float4*)(x + (size_t)(m0 + row) * D_ + k0 + c4);
            As[c4 + 0][row] = v.x; As[c4 + 1][row] = v.y;
            As[c4 + 2][row] = v.z; As[c4 + 3][row] = v.w;
        }
        {
            int q   = tx;
            int row = q >> 2;
            int c4  = (q & 3) * 4;
            float4 v = *(const float4*)(Wi + (size_t)(n0 + row) * D_ + k0 + c4);
            Bs[c4 + 0][row] = v.x; Bs[c4 + 1][row] = v.y;
            Bs[c4 + 2][row] = v.z; Bs[c4 + 3][row] = v.w;
        }
        __syncthreads();

#pragma unroll
        for (int k = 0; k < IT_K; ++k) {
            ull au0x = *(const ull*)&As[k][tm * 8];
            ull au0y = *(const ull*)&As[k][tm * 8 + 2];
            ull au1x = *(const ull*)&As[k][tm * 8 + 4];
            ull au1y = *(const ull*)&As[k][tm * 8 + 6];
            float4 bv = *(const float4*)&Bs[k][tn * 4];
            ull bp0 = pk2(bv.x, bv.x), bp1 = pk2(bv.y, bv.y);
            ull bp2 = pk2(bv.z, bv.z), bp3 = pk2(bv.w, bv.w);
            acc[0][0] = fma2(au0x, bp0, acc[0][0]);
            acc[0][1] = fma2(au0x, bp1, acc[0][1]);
            acc[0][2] = fma2(au0x, bp2, acc[0][2]);
            acc[0][3] = fma2(au0x, bp3, acc[0][3]);
            acc[1][0] = fma2(au0y, bp0, acc[1][0]);
            acc[1][1] = fma2(au0y, bp1, acc[1][1]);
            acc[1][2] = fma2(au0y, bp2, acc[1][2]);
            acc[1][3] = fma2(au0y, bp3, acc[1][3]);
            acc[2][0] = fma2(au1x, bp0, acc[2][0]);
            acc[2][1] = fma2(au1x, bp1, acc[2][1]);
            acc[2][2] = fma2(au1x, bp2, acc[2][2]);
            acc[2][3] = fma2(au1x, bp3, acc[2][3]);
            acc[3][0] = fma2(au1y, bp0, acc[3][0]);
            acc[3][1] = fma2(au1y, bp1, acc[3][1]);
            acc[3][2] = fma2(au1y, bp2, acc[3][2]);
            acc[3][3] = fma2(au1y, bp3, acc[3][3]);
        }
        __syncthreads();
    }

    // Epilogue: unpack pairs, add bias, scatter to g_xg[s][b][n]
    float4 biv = *(const float4*)(bi + n0 + tn * 4);
#pragma unroll
    for (int i = 0; i < 4; ++i) {
        float lo[4], hi[4];
#pragma unroll
        for (int j = 0; j < 4; ++j) upk2(acc[i][j], lo[j], hi[j]);
        int r0 = m0 + tm * 8 + 2 * i;
#pragma unroll
        for (int r = 0; r < 2; ++r) {
            int m  = r0 + r;
            int s  = m & (S_ - 1);
            int bb = m >> 9;
            float4 o;
            o.x = (r ? hi[0] : lo[0]) + biv.x;
            o.y = (r ? hi[1] : lo[1]) + biv.y;
            o.z = (r ? hi[2] : lo[2]) + biv.z;
            o.w = (r ? hi[3] : lo[3]) + biv.w;
            *(float4*)(g_xg + ((size_t)s * B_ + bb) * G4 + n0 + tn * 4) = o;
        }
    }
}

// ---------------------------------------------------------------------------
// init_h: g_hT[0][k][b] = h0[k]  (broadcast over batch)
// ---------------------------------------------------------------------------
__global__ void init_h(const float* __restrict__ h0)
{
    int i = blockIdx.x * blockDim.x + threadIdx.x;   // 65536 threads
    g_hT[0][i >> 6][i & 63] = h0[i >> 6];
}

// ---------------------------------------------------------------------------
// Persistent recurrence kernel: 128 CTAs (1/SM), 256 threads.
// Each CTA owns 8 hidden units (32 gate cols). Wh slice (128 KB) resident in
// SMEM for all 512 steps. h ping-pongs through g_hT (L2, __ldcg). Grid
// barrier between steps.
// SMEM: Ws[1024][32] (128K) | Hs[2][64][68] (34K) | GsT[32][68] (8.5K)
// ---------------------------------------------------------------------------
#define HS_PAD 68
#define LSTM_SMEM ((1024*32 + 2*64*HS_PAD + 32*HS_PAD) * 4)

__global__ void __launch_bounds__(256, 1)
lstm_persist(const float* __restrict__ Wh,
             const float* __restrict__ bh,
             const float* __restrict__ c0,
             float* __restrict__ hidden)
{
    extern __shared__ float sm[];
    float* Ws  = sm;                      // [k][n]  k=0..1023, n=0..31
    float* Hs  = sm + 1024 * 32;          // [2][64][68]
    float* GsT = Hs + 2 * 64 * HS_PAD;    // [32][68]  gates [col][row]

    const int tx = threadIdx.x;
    const int j0 = blockIdx.x * 8;

    // ---- Load Wh slice into SMEM (once) ----
    {
        int n = tx & 31, seg = tx >> 5;          // 8 segments of 128 k
        int gate = n >> 3, jw = n & 7;
        const float* wrow = Wh + (size_t)(gate * H_ + j0 + jw) * H_ + seg * 128;
#pragma unroll 4
        for (int kk = 0; kk < 128; kk += 4) {
            float4 v = *(const float4*)(wrow + kk);
            int k = seg * 128 + kk;
            Ws[(k + 0) * 32 + n] = v.x;
            Ws[(k + 1) * 32 + n] = v.y;
            Ws[(k + 2) * 32 + n] = v.z;
            Ws[(k + 3) * 32 + n] = v.w;
        }
    }

    // ---- Per-thread cell-update constants ----
    const int jj  = tx & 7;
    const int bb0 = tx >> 3;                 // 0..31 (l=1 adds 32)
    const int j   = j0 + jj;
    float bhv[4], cst[2];
#pragma unroll
    for (int g = 0; g < 4; ++g) bhv[g] = bh[g * H_ + j];
    cst[0] = cst[1] = c0[j];

    const int tn = tx & 15;                  // 16 col-pairs
    const int tm = tx >> 4;                  // 16 row-quads
    const int klf = tx >> 2;                 // Hs fill: row 0..63
    const int qf  = (tx & 3) * 16;           // Hs fill: col quarter

    unsigned bar_base;
    if (tx == 0) bar_base = *(volatile unsigned*)&g_bar_sense;
    __syncthreads();

    for (int t = 0; t < S_; ++t) {
        const float* ghr = &g_hT[t & 1][0][0];

        // Prefetch xg for this step's cell update (DRAM latency hidden by GEMM)
        float xgv[2][4];
#pragma unroll
        for (int l = 0; l < 2; ++l) {
            const float* xp = g_xg + ((size_t)t * B_ + (bb0 + l * 32)) * G4 + j;
#pragma unroll
            for (int g = 0; g < 4; ++g) xgv[l][g] = __ldg(xp + g * H_);
        }

        // ---- GEMM: gates[b][n] = sum_k h[k][b] * Ws[k][n] ----
        ull acc00 = 0, acc01 = 0, acc10 = 0, acc11 = 0;

        // fill chunk 0
        {
            const float* src = ghr + (size_t)klf * B_ + qf;
            float4 v0 = __ldcg((const float4*)(src + 0));
            float4 v1 = __ldcg((const float4*)(src + 4));
            float4 v2 = __ldcg((const float4*)(src + 8));
            float4 v3 = __ldcg((const float4*)(src + 12));
            float* dst = Hs + klf * HS_PAD + qf;
            *(float4*)(dst + 0) = v0; *(float4*)(dst + 4)  = v1;
            *(float4*)(dst + 8) = v2; *(float4*)(dst + 12) = v3;
        }
        __syncthreads();

#pragma unroll 1
        for (int c = 0; c < 16; ++c) {
            float4 p0, p1, p2, p3;
            if (c < 15) {
                const float* src = ghr + (size_t)((c + 1) * 64 + klf) * B_ + qf;
                p0 = __ldcg((const float4*)(src + 0));
                p1 = __ldcg((const float4*)(src + 4));
                p2 = __ldcg((const float4*)(src + 8));
                p3 = __ldcg((const float4*)(src + 12));
            }
            const float* hb = Hs + (c & 1) * 64 * HS_PAD;
            const float* wb = Ws + c * 64 * 32;
#pragma unroll 16
            for (int kl = 0; kl < 64; ++kl) {
                ull aux = *(const ull*)(hb + kl * HS_PAD + tm * 4);
                ull auy = *(const ull*)(hb + kl * HS_PAD + tm * 4 + 2);
                float2 bv = *(const float2*)(wb + kl * 32 + tn * 2);
                ull bp0 = pk2(bv.x, bv.x);
                ull bp1 = pk2(bv.y, bv.y);
                acc00 = fma2(aux, bp0, acc00);
                acc01 = fma2(aux, bp1, acc01);
                acc10 = fma2(auy, bp0, acc10);
                acc11 = fma2(auy, bp1, acc11);
            }
            if (c < 15) {
                float* dst = Hs + ((c + 1) & 1) * 64 * HS_PAD + klf * HS_PAD + qf;
                *(float4*)(dst + 0) = p0; *(float4*)(dst + 4)  = p1;
                *(float4*)(dst + 8) = p2; *(float4*)(dst + 12) = p3;
            }
            __syncthreads();
        }

        // ---- Scatter gate accs to GsT[col][row] (pairs are consecutive rows) ----
        *(ull*)(GsT + (tn * 2 + 0) * HS_PAD + tm * 4)     = acc00;
        *(ull*)(GsT + (tn * 2 + 0) * HS_PAD + tm * 4 + 2) = acc10;
        *(ull*)(GsT + (tn * 2 + 1) * HS_PAD + tm * 4)     = acc01;
        *(ull*)(GsT + (tn * 2 + 1) * HS_PAD + tm * 4 + 2) = acc11;
        __syncthreads();

        // ---- Cell update: each thread owns (bb0, jj) and (bb0+32, jj) ----
        float* ghw = &g_hT[(t + 1) & 1][0][0];
#pragma unroll
        for (int l = 0; l < 2; ++l) {
            int bb = bb0 + l * 32;
            float iv = GsT[(0 * 8 + jj) * HS_PAD + bb] + xgv[l][0] + bhv[0];
            float fv = GsT[(1 * 8 + jj) * HS_PAD + bb] + xgv[l][1] + bhv[1];
            float gv = GsT[(2 * 8 + jj) * HS_PAD + bb] + xgv[l][2] + bhv[2];
            float ov = GsT[(3 * 8 + jj) * HS_PAD + bb] + xgv[l][3] + bhv[3];

            float is = 1.0f / (1.0f + expf(-iv));
            float fs = 1.0f / (1.0f + expf(-fv));
            float gt = tanhf(gv);
            float os = 1.0f / (1.0f + expf(-ov));

            float cn = fs * cst[l] + is * gt;
            cst[l] = cn;
            float h = os * tanhf(cn);

            ghw[(size_t)j * B_ + bb] = h;                       // for next step
            hidden[((size_t)bb * S_ + t) * H_ + j] = h;         // output
            if (t == S_ - 1) g_c[bb * H_ + j] = cn;
        }

        // ---- Grid barrier (sense-reversing) ----
        __threadfence();
        __syncthreads();
        if (tx == 0) {
            unsigned target = bar_base + (unsigned)t + 1u;
            unsigned arr = atomicAdd(&g_bar_count, 1u);
            if (arr == NCTA - 1) {
                g_bar_count = 0;
                __threadfence();
                atomicExch(&g_bar_sense, target);
            } else {
                while (*(volatile unsigned*)&g_bar_sense != target) __nanosleep(32);
            }
            __threadfence();
        }
        __syncthreads();
    }
}

// ---------------------------------------------------------------------------
// Finalize: copy h_final (= hidden_seq[:,S-1,:]) and c_final into d_out tail.
// ---------------------------------------------------------------------------
__global__ void finalize(const float* __restrict__ hidden, float* __restrict__ out_hc)
{
    int i = blockIdx.x * blockDim.x + threadIdx.x;
    int n = B_ * H_;
    if (i < n) {
        int bb = i / H_, jq = i % H_;
        out_hc[i] = hidden[((size_t)bb * S_ + (S_ - 1)) * H_ + jq];
    } else if (i < 2 * n) {
        out_hc[i] = g_c[i - n];
    }
}

// ---------------------------------------------------------------------------
extern "C" void kernel_launch(void* const* d_in, const int* in_sizes, int n_in,
                              void* d_out, int out_size)
{
    const float* x  = (const float*)d_in[0];
    const float* h0 = (const float*)d_in[1];
    const float* c0 = (const float*)d_in[2];
    const float* Wi = (const float*)d_in[3];
    const float* bi = (const float*)d_in[4];
    const float* Wh = (const float*)d_in[5];
    const float* bh = (const float*)d_in[6];
    float* out = (float*)d_out;

    // Phase 1: input projection into g_xg
    dim3 g1(G4 / IT_N, M_TOT / IT_M);   // (64, 256)
    input_gemm<<<g1, 256>>>(x, Wi, bi);

    // Phase 1b: h0 broadcast into g_hT[0]
    init_h<<<(B_ * H_) / 256, 256>>>(h0);

    // Phase 2: persistent recurrence (single launch, grid barrier per step)
    cudaFuncSetAttribute(lstm_persist, cudaFuncAttributeMaxDynamicSharedMemorySize,
                         LSTM_SMEM);
    lstm_persist<<<NCTA, 256, LSTM_SMEM>>>(Wh, bh, c0, out);

    // Phase 3: final (h, c)
    finalize<<<(2 * B_ * H_ + 255) / 256, 256>>>(out, out + (size_t)B_ * S_ * H_);
}

// round 3
// speedup vs baseline: 1.3555x; 1.0007x over previous
#include <cuda_runtime.h>
#include <math.h>

typedef unsigned long long ull;

// Problem constants
#define B_   64
#define S_   512
#define D_   1024
#define H_   1024
#define G4   (4 * H_)        // 4096
#define M_TOT (B_ * S_)      // 32768
#define NCTA 128

// Scratch (allocation-free rule: __device__ globals)
__device__ float g_xg[(size_t)S_ * B_ * G4];   // [S][B][4H]  = 512 MB
__device__ float g_c[B_ * H_];                 // final cell state [B][H]
__device__ float g_hT[2][H_][B_];              // ping-pong h, transposed [j][b]
__device__ unsigned g_bar_sense;               // grid barrier generation
__device__ unsigned g_bar_count;               // grid barrier arrivals

// ---------------------------------------------------------------------------
// Packed fp32x2 helpers (Blackwell FFMA2 — only reachable via PTX)
// ---------------------------------------------------------------------------
__device__ __forceinline__ ull pk2(float lo, float hi) {
    ull r; asm("mov.b64 %0, {%1, %2};" : "=l"(r) : "f"(lo), "f"(hi)); return r;
}
__device__ __forceinline__ ull fma2(ull a, ull b, ull c) {
    ull d; asm("fma.rn.f32x2 %0, %1, %2, %3;" : "=l"(d) : "l"(a), "l"(b), "l"(c)); return d;
}
__device__ __forceinline__ void upk2(ull v, float& lo, float& hi) {
    asm("mov.b64 {%0, %1}, %2;" : "=f"(lo), "=f"(hi) : "l"(v));
}

// ---------------------------------------------------------------------------
// Kernel A: input projection  xg[s][b][n] = sum_k x[m][k]*Wi[n][k] + bi[n]
// Tile 128(M) x 64(N), TK=16, 256 threads, 8x4 per-thread via 4x(Mpair)x4 FFMA2
// ---------------------------------------------------------------------------
#define IT_M 128
#define IT_N 64
#define IT_K 16

__global__ __launch_bounds__(256)
void input_gemm(const float* __restrict__ x,
                const float* __restrict__ Wi,
                const float* __restrict__ bi)
{
    __shared__ float As[IT_K][IT_M + 4];
    __shared__ float Bs[IT_K][IT_N + 4];

    const int m0 = blockIdx.y * IT_M;
    const int n0 = blockIdx.x * IT_N;
    const int tx = threadIdx.x;
    const int tn = tx & 15;
    const int tm = tx >> 4;

    ull acc[4][4];
#pragma unroll
    for (int i = 0; i < 4; ++i)
#pragma unroll
        for (int j = 0; j < 4; ++j) acc[i][j] = 0ULL;

    for (int k0 = 0; k0 < D_; k0 += IT_K) {
#pragma unroll
        for (int l = 0; l < 2; ++l) {
            int q   = tx * 2 + l;
            int row = q >> 2;
            int c4  = (q & 3) * 4;
            float4 v = *(const float4*)(x + (size_t)(m0 + row) * D_ + k0 + c4);
            As[c4 + 0][row] = v.x; As[c4 + 1][row] = v.y;
            As[c4 + 2][row] = v.z; As[c4 + 3][row] = v.w;
        }
        {
            int q   = tx;
            int row = q >> 2;
            int c4  = (q & 3) * 4;
            float4 v = *(const float4*)(Wi + (size_t)(n0 + row) * D_ + k0 + c4);
            Bs[c4 + 0][row] = v.x; Bs[c4 + 1][row] = v.y;
            Bs[c4 + 2][row] = v.z; Bs[c4 + 3][row] = v.w;
        }
        __syncthreads();

#pragma unroll
        for (int k = 0; k < IT_K; ++k) {
            ull au0x = *(const ull*)&As[k][tm * 8];
            ull au0y = *(const ull*)&As[k][tm * 8 + 2];
            ull au1x = *(const ull*)&As[k][tm * 8 + 4];
            ull au1y = *(const ull*)&As[k][tm * 8 + 6];
            float4 bv = *(const float4*)&Bs[k][tn * 4];
            ull bp0 = pk2(bv.x, bv.x), bp1 = pk2(bv.y, bv.y);
            ull bp2 = pk2(bv.z, bv.z), bp3 = pk2(bv.w, bv.w);
            acc[0][0] = fma2(au0x, bp0, acc[0][0]);
            acc[0][1] = fma2(au0x, bp1, acc[0][1]);
            acc[0][2] = fma2(au0x, bp2, acc[0][2]);
            acc[0][3] = fma2(au0x, bp3, acc[0][3]);
            acc[1][0] = fma2(au0y, bp0, acc[1][0]);
            acc[1][1] = fma2(au0y, bp1, acc[1][1]);
            acc[1][2] = fma2(au0y, bp2, acc[1][2]);
            acc[1][3] = fma2(au0y, bp3, acc[1][3]);
            acc[2][0] = fma2(au1x, bp0, acc[2][0]);
            acc[2][1] = fma2(au1x, bp1, acc[2][1]);
            acc[2][2] = fma2(au1x, bp2, acc[2][2]);
            acc[2][3] = fma2(au1x, bp3, acc[2][3]);
            acc[3][0] = fma2(au1y, bp0, acc[3][0]);
            acc[3][1] = fma2(au1y, bp1, acc[3][1]);
            acc[3][2] = fma2(au1y, bp2, acc[3][2]);
            acc[3][3] = fma2(au1y, bp3, acc[3][3]);
        }
        __syncthreads();
    }

    // Epilogue: unpack pairs, add bias, scatter to g_xg[s][b][n]
    float4 biv = *(const float4*)(bi + n0 + tn * 4);
#pragma unroll
    for (int i = 0; i < 4; ++i) {
        float lo[4], hi[4];
#pragma unroll
        for (int j = 0; j < 4; ++j) upk2(acc[i][j], lo[j], hi[j]);
        int r0 = m0 + tm * 8 + 2 * i;
#pragma unroll
        for (int r = 0; r < 2; ++r) {
            int m  = r0 + r;
            int s  = m & (S_ - 1);
            int bb = m >> 9;
            float4 o;
            o.x = (r ? hi[0] : lo[0]) + biv.x;
            o.y = (r ? hi[1] : lo[1]) + biv.y;
            o.z = (r ? hi[2] : lo[2]) + biv.z;
            o.w = (r ? hi[3] : lo[3]) + biv.w;
            *(float4*)(g_xg + ((size_t)s * B_ + bb) * G4 + n0 + tn * 4) = o;
        }
    }
}

// ---------------------------------------------------------------------------
// init_h: g_hT[0][k][b] = h0[k]  (broadcast over batch)
// ---------------------------------------------------------------------------
__global__ void init_h(const float* __restrict__ h0)
{
    int i = blockIdx.x * blockDim.x + threadIdx.x;   // 65536 threads
    g_hT[0][i >> 6][i & 63] = h0[i >> 6];
}

// ---------------------------------------------------------------------------
// Persistent recurrence kernel: 128 CTAs (1/SM), 256 threads.
// Each CTA owns 8 hidden units (32 gate cols). Wh slice (128 KB) resident in
// SMEM for all 512 steps. h ping-pongs through g_hT (L2, __ldcg). Grid
// barrier between steps.
// SMEM: Ws[1024][32] (128K) | Hs[2][64][68] (34K) | GsT[32][68] (8.5K)
// ---------------------------------------------------------------------------
#define HS_PAD 68
#define LSTM_SMEM ((1024*32 + 2*64*HS_PAD + 32*HS_PAD) * 4)

__global__ void __launch_bounds__(256, 1)
lstm_persist(const float* __restrict__ Wh,
             const float* __restrict__ bh,
             const float* __restrict__ c0,
             float* __restrict__ hidden)
{
    extern __shared__ float sm[];
    float* Ws  = sm;                      // [k][n]  k=0..1023, n=0..31
    float* Hs  = sm + 1024 * 32;          // [2][64][68]
    float* GsT = Hs + 2 * 64 * HS_PAD;    // [32][68]  gates [col][row]

    const int tx = threadIdx.x;
    const int j0 = blockIdx.x * 8;

    // ---- Load Wh slice into SMEM (once) ----
    {
        int n = tx & 31, seg = tx >> 5;          // 8 segments of 128 k
        int gate = n >> 3, jw = n & 7;
        const float* wrow = Wh + (size_t)(gate * H_ + j0 + jw) * H_ + seg * 128;
#pragma unroll 4
        for (int kk = 0; kk < 128; kk += 4) {
            float4 v = *(const float4*)(wrow + kk);
            int k = seg * 128 + kk;
            Ws[(k + 0) * 32 + n] = v.x;
            Ws[(k + 1) * 32 + n] = v.y;
            Ws[(k + 2) * 32 + n] = v.z;
            Ws[(k + 3) * 32 + n] = v.w;
        }
    }

    // ---- Per-thread cell-update constants ----
    const int jj  = tx & 7;
    const int bb0 = tx >> 3;                 // 0..31 (l=1 adds 32)
    const int j   = j0 + jj;
    float bhv[4], cst[2];
#pragma unroll
    for (int g = 0; g < 4; ++g) bhv[g] = bh[g * H_ + j];
    cst[0] = cst[1] = c0[j];

    const int tn = tx & 15;                  // 16 col-pairs
    const int tm = tx >> 4;                  // 16 row-quads
    const int klf = tx >> 2;                 // Hs fill: row 0..63
    const int qf  = (tx & 3) * 16;           // Hs fill: col quarter

    unsigned bar_base;
    if (tx == 0) bar_base = *(volatile unsigned*)&g_bar_sense;
    __syncthreads();

    for (int t = 0; t < S_; ++t) {
        const float* ghr = &g_hT[t & 1][0][0];

        // Prefetch xg for this step's cell update (DRAM latency hidden by GEMM)
        float xgv[2][4];
#pragma unroll
        for (int l = 0; l < 2; ++l) {
            const float* xp = g_xg + ((size_t)t * B_ + (bb0 + l * 32)) * G4 + j;
#pragma unroll
            for (int g = 0; g < 4; ++g) xgv[l][g] = __ldg(xp + g * H_);
        }

        // ---- GEMM: gates[b][n] = sum_k h[k][b] * Ws[k][n] ----
        ull acc00 = 0, acc01 = 0, acc10 = 0, acc11 = 0;

        // fill chunk 0
        {
            const float* src = ghr + (size_t)klf * B_ + qf;
            float4 v0 = __ldcg((const float4*)(src + 0));
            float4 v1 = __ldcg((const float4*)(src + 4));
            float4 v2 = __ldcg((const float4*)(src + 8));
            float4 v3 = __ldcg((const float4*)(src + 12));
            float* dst = Hs + klf * HS_PAD + qf;
            *(float4*)(dst + 0) = v0; *(float4*)(dst + 4)  = v1;
            *(float4*)(dst + 8) = v2; *(float4*)(dst + 12) = v3;
        }
        __syncthreads();

#pragma unroll 1
        for (int c = 0; c < 16; ++c) {
            float4 p0, p1, p2, p3;
            if (c < 15) {
                const float* src = ghr + (size_t)((c + 1) * 64 + klf) * B_ + qf;
                p0 = __ldcg((const float4*)(src + 0));
                p1 = __ldcg((const float4*)(src + 4));
                p2 = __ldcg((const float4*)(src + 8));
                p3 = __ldcg((const float4*)(src + 12));
            }
            const float* hb = Hs + (c & 1) * 64 * HS_PAD;
            const float* wb = Ws + c * 64 * 32;
#pragma unroll 16
            for (int kl = 0; kl < 64; ++kl) {
                ull aux = *(const ull*)(hb + kl * HS_PAD + tm * 4);
                ull auy = *(const ull*)(hb + kl * HS_PAD + tm * 4 + 2);
                float2 bv = *(const float2*)(wb + kl * 32 + tn * 2);
                ull bp0 = pk2(bv.x, bv.x);
                ull bp1 = pk2(bv.y, bv.y);
                acc00 = fma2(aux, bp0, acc00);
                acc01 = fma2(aux, bp1, acc01);
                acc10 = fma2(auy, bp0, acc10);
                acc11 = fma2(auy, bp1, acc11);
            }
            if (c < 15) {
                float* dst = Hs + ((c + 1) & 1) * 64 * HS_PAD + klf * HS_PAD + qf;
                *(float4*)(dst + 0) = p0; *(float4*)(dst + 4)  = p1;
                *(float4*)(dst + 8) = p2; *(float4*)(dst + 12) = p3;
            }
            __syncthreads();
        }

        // ---- Scatter gate accs to GsT[col][row] (pairs are consecutive rows) ----
        *(ull*)(GsT + (tn * 2 + 0) * HS_PAD + tm * 4)     = acc00;
        *(ull*)(GsT + (tn * 2 + 0) * HS_PAD + tm * 4 + 2) = acc10;
        *(ull*)(GsT + (tn * 2 + 1) * HS_PAD + tm * 4)     = acc01;
        *(ull*)(GsT + (tn * 2 + 1) * HS_PAD + tm * 4 + 2) = acc11;
        __syncthreads();

        // ---- Cell update: each thread owns (bb0, jj) and (bb0+32, jj) ----
        float* ghw = &g_hT[(t + 1) & 1][0][0];
#pragma unroll
        for (int l = 0; l < 2; ++l) {
            int bb = bb0 + l * 32;
            float iv = GsT[(0 * 8 + jj) * HS_PAD + bb] + xgv[l][0] + bhv[0];
            float fv = GsT[(1 * 8 + jj) * HS_PAD + bb] + xgv[l][1] + bhv[1];
            float gv = GsT[(2 * 8 + jj) * HS_PAD + bb] + xgv[l][2] + bhv[2];
            float ov = GsT[(3 * 8 + jj) * HS_PAD + bb] + xgv[l][3] + bhv[3];

            float is = 1.0f / (1.0f + expf(-iv));
            float fs = 1.0f / (1.0f + expf(-fv));
            float gt = tanhf(gv);
            float os = 1.0f / (1.0f + expf(-ov));

            float cn = fs * cst[l] + is * gt;
            cst[l] = cn;
            float h = os * tanhf(cn);

            ghw[(size_t)j * B_ + bb] = h;                       // for next step
            hidden[((size_t)bb * S_ + t) * H_ + j] = h;         // output
            if (t == S_ - 1) g_c[bb * H_ + j] = cn;
        }

        // ---- Grid barrier (sense-reversing) ----
        __threadfence();
        __syncthreads();
        if (tx == 0) {
            unsigned target = bar_base + (unsigned)t + 1u;
            unsigned arr = atomicAdd(&g_bar_count, 1u);
            if (arr == NCTA - 1) {
                g_bar_count = 0;
                __threadfence();
                atomicExch(&g_bar_sense, target);
            } else {
                while (*(volatile unsigned*)&g_bar_sense != target) __nanosleep(32);
            }
            __threadfence();
        }
        __syncthreads();
    }
}

// ---------------------------------------------------------------------------
// Finalize: copy h_final (= hidden_seq[:,S-1,:]) and c_final into d_out tail.
// ---------------------------------------------------------------------------
__global__ void finalize(const float* __restrict__ hidden, float* __restrict__ out_hc)
{
    int i = blockIdx.x * blockDim.x + threadIdx.x;
    int n = B_ * H_;
    if (i < n) {
        int bb = i / H_, jq = i % H_;
        out_hc[i] = hidden[((size_t)bb * S_ + (S_ - 1)) * H_ + jq];
    } else if (i < 2 * n) {
        out_hc[i] = g_c[i - n];
    }
}

// ---------------------------------------------------------------------------
extern "C" void kernel_launch(void* const* d_in, const int* in_sizes, int n_in,
                              void* d_out, int out_size)
{
    const float* x  = (const float*)d_in[0];
    const float* h0 = (const float*)d_in[1];
    const float* c0 = (const float*)d_in[2];
    const float* Wi = (const float*)d_in[3];
    const float* bi = (const float*)d_in[4];
    const float* Wh = (const float*)d_in[5];
    const float* bh = (const float*)d_in[6];
    float* out = (float*)d_out;

    // Phase 1: input projection into g_xg
    dim3 g1(G4 / IT_N, M_TOT / IT_M);   // (64, 256)
    input_gemm<<<g1, 256>>>(x, Wi, bi);

    // Phase 1b: h0 broadcast into g_hT[0]
    init_h<<<(B_ * H_) / 256, 256>>>(h0);

    // Phase 2: persistent recurrence (single launch, grid barrier per step)
    cudaFuncSetAttribute(lstm_persist, cudaFuncAttributeMaxDynamicSharedMemorySize,
                         LSTM_SMEM);
    lstm_persist<<<NCTA, 256, LSTM_SMEM>>>(Wh, bh, c0, out);

    // Phase 3: final (h, c)
    finalize<<<(2 * B_ * H_ + 255) / 256, 256>>>(out, out + (size_t)B_ * S_ * H_);
}